// round 12
// baseline (speedup 1.0000x reference)
#include <cuda_runtime.h>
#include <cuda_bf16.h>
#include <cstdint>

// ===========================================================================
// GCN: out = Anorm @ relu(Anorm @ relu(Anorm @ (x W1) + b1) W2 + b2) W3 + b3
// R11 base (262.4us) + GEMM3 retiled to 128x64 (256 CTAs, 2/SM) +
// vectorized clear + uint4 build_rows loads. GEMM1/2 inner loop untouched.
// ===========================================================================

#define NNODES 8192
#define FDIM   512
#define WORDS_PER_ROW 256
#define MAXDEG 192
#define QMAGICF 8421376.0f    // 2^23 + 32768

__device__ unsigned int g_bits[NNODES * WORDS_PER_ROW];   // 8 MB
__device__ unsigned int g_self[WORDS_PER_ROW];
__device__ float g_dinv[NNODES];
__device__ float g_selfcoef[NNODES];
__device__ int   g_cols[NNODES * MAXDEG];
__device__ int   g_cnt[NNODES];
__device__ int   g_is64;
__device__ __nv_bfloat16 g_ah[NNODES * FDIM];             // 8 MB activation hi
__device__ __nv_bfloat16 g_al[NNODES * FDIM];             // 8 MB activation lo
__device__ __nv_bfloat16 g_bh[655360];                    // W1|W2|W3 hi, n-major
__device__ __nv_bfloat16 g_bl[655360];                    // W1|W2|W3 lo
__device__ unsigned short g_q[NNODES * FDIM];             // quantized GEMM out
__device__ float g_qs[NNODES * 4];                        // per-(row, col-block) scale

// ===========================================================================
// K0: clear bit matrix (uint4 stores) + int64 detect
// NOTE: the g_is64=1 store is latency-ordered before any detect store (detect
// stores depend on a ~500cyc global load; the =1 store issues immediately).
// ===========================================================================
__global__ void k_clear_detect(const int* __restrict__ ei, int E) {
    int i4 = blockIdx.x * blockDim.x + threadIdx.x;   // [0, 524288)
    if (i4 == 0) g_is64 = 1;
    int row = i4 >> 6;                                // 64 uint4 per row
    int lw  = (i4 & 63) * 4;                          // first word covered
    int dw  = row >> 5;                               // diagonal word index
    uint4 v = make_uint4(0u, 0u, 0u, 0u);
    if (dw >= lw && dw < lw + 4)
        ((unsigned*)&v)[dw - lw] = 1u << (row & 31);
    ((uint4*)g_bits)[i4] = v;
    if (i4 < 64) ((uint4*)g_self)[i4] = make_uint4(0u, 0u, 0u, 0u);
    if (i4 < E) {
        if (ei[2 * i4 + 1] != 0) g_is64 = 0;
    }
}

// ===========================================================================
// K1: scatter edges (set semantics)
// ===========================================================================
__global__ void k_scatter(const int* __restrict__ w, int E) {
    int i = blockIdx.x * blockDim.x + threadIdx.x;
    if (i >= E) return;
    int a, b;
    if (g_is64) { a = w[2 * i]; b = w[2 * E + 2 * i]; }
    else        { a = w[i];     b = w[E + i]; }
    if ((unsigned)a >= NNODES || (unsigned)b >= NNODES) return;
    atomicOr(&g_bits[(size_t)a * WORDS_PER_ROW + (b >> 5)], 1u << (b & 31));
    atomicOr(&g_bits[(size_t)b * WORDS_PER_ROW + (a >> 5)], 1u << (a & 31));
    if (a == b) atomicOr(&g_self[a >> 5], 1u << (a & 31));
}

// ===========================================================================
// K2: per-row compaction + degree normalization (uint4 row loads)
// ===========================================================================
__global__ void k_build_rows() {
    int warp = (blockIdx.x * blockDim.x + threadIdx.x) >> 5;
    int lane = threadIdx.x & 31;
    if (warp >= NNODES) return;
    int row = warp;

    const uint4* b4 = (const uint4*)&g_bits[(size_t)row * WORDS_PER_ROW];
    uint4 u0 = b4[lane * 2];
    uint4 u1 = b4[lane * 2 + 1];
    unsigned int w[8] = {u0.x, u0.y, u0.z, u0.w, u1.x, u1.y, u1.z, u1.w};

    int dw = row >> 5;
    if ((dw >> 3) == lane) w[dw & 7] &= ~(1u << (row & 31));

    unsigned int cnt = 0;
#pragma unroll
    for (int t = 0; t < 8; t++) cnt += __popc(w[t]);

    unsigned int incl = cnt;
#pragma unroll
    for (int d = 1; d < 32; d <<= 1) {
        unsigned int v = __shfl_up_sync(0xFFFFFFFFu, incl, d);
        if (lane >= d) incl += v;
    }
    unsigned int excl  = incl - cnt;
    unsigned int total = __shfl_sync(0xFFFFFFFFu, incl, 31);

    int* cols = &g_cols[(size_t)row * MAXDEG];
    unsigned int o = excl;
#pragma unroll
    for (int t = 0; t < 8; t++) {
        unsigned int bits = w[t];
        int colbase = (lane * 8 + t) * 32;
        while (bits) {
            int b = __ffs(bits) - 1;
            bits &= bits - 1;
            if (o < MAXDEG) cols[o] = colbase + b;
            o++;
        }
    }

    if (lane == 0) {
        int self = (g_self[row >> 5] >> (row & 31)) & 1;
        float deg = (float)total + 1.0f + (float)self;
        float di = rsqrtf(deg);
        g_dinv[row] = di;
        g_selfcoef[row] = (1.0f + (float)self) * di;
        g_cnt[row] = (int)(total < MAXDEG ? total : MAXDEG);
    }
}

// ===========================================================================
// K3: expandX + expandB (one kernel, disjoint block ranges)
// ===========================================================================
__device__ __forceinline__ uint32_t packbf2(float x, float y) {
    __nv_bfloat162 t = __floats2bfloat162_rn(x, y);
    return *(uint32_t*)&t;
}

__global__ void k_expand_all(const float* __restrict__ X,
                             const float* __restrict__ W1,
                             const float* __restrict__ W2,
                             const float* __restrict__ W3) {
    int bid = blockIdx.x;
    if (bid < 4096) {
        int idx = bid * 256 + threadIdx.x;           // over (8192*512)/4
        float4 v = ((const float4*)X)[idx];
        float hx = __bfloat162float(__float2bfloat16_rn(v.x));
        float hy = __bfloat162float(__float2bfloat16_rn(v.y));
        float hz = __bfloat162float(__float2bfloat16_rn(v.z));
        float hw = __bfloat162float(__float2bfloat16_rn(v.w));
        ((uint2*)g_ah)[idx] = make_uint2(packbf2(v.x, v.y), packbf2(v.z, v.w));
        ((uint2*)g_al)[idx] = make_uint2(packbf2(v.x - hx, v.y - hy),
                                         packbf2(v.z - hz, v.w - hw));
    } else {
        int idx = (bid - 4096) * 256 + threadIdx.x;  // over 655360
        if (idx >= 655360) return;
        const float* W;
        int Ncol, local;
        if (idx < 262144)      { W = W1; Ncol = 512; local = idx; }
        else if (idx < 524288) { W = W2; Ncol = 512; local = idx - 262144; }
        else                   { W = W3; Ncol = 256; local = idx - 524288; }
        int n = local >> 9;
        int k = local & 511;
        float v = W[(size_t)k * Ncol + n];
        __nv_bfloat16 hi = __float2bfloat16_rn(v);
        __nv_bfloat16 lo = __float2bfloat16_rn(v - __bfloat162float(hi));
        g_bh[idx] = hi;
        g_bl[idx] = lo;
    }
}

// ===========================================================================
// GEMM: C = A @ W via ah*bh + ah*bl + al*bh. 2 CTAs/SM, single-sync pipeline.
// Template NTILE (128 or 64) = CTA n-tile width. Warp tile 32 x NTILE/2.
// ===========================================================================
__device__ __forceinline__ void cp16(uint32_t saddr, const void* g) {
    asm volatile("cp.async.cg.shared.global [%0], [%1], 16;" :: "r"(saddr), "l"(g));
}
__device__ __forceinline__ void cp_commit() { asm volatile("cp.async.commit_group;"); }
template <int N> __device__ __forceinline__ void cp_wait() {
    asm volatile("cp.async.wait_group %0;" :: "n"(N));
}
__device__ __forceinline__ void ldsm4(uint32_t& r0, uint32_t& r1, uint32_t& r2,
                                      uint32_t& r3, uint32_t addr) {
    asm volatile("ldmatrix.sync.aligned.m8n8.x4.shared.b16 {%0,%1,%2,%3}, [%4];"
                 : "=r"(r0), "=r"(r1), "=r"(r2), "=r"(r3) : "r"(addr));
}
__device__ __forceinline__ void mma16816(float* c, uint32_t a0, uint32_t a1,
                                         uint32_t a2, uint32_t a3,
                                         uint32_t b0, uint32_t b1) {
    asm volatile(
        "mma.sync.aligned.m16n8k16.row.col.f32.bf16.bf16.f32 "
        "{%0,%1,%2,%3}, {%4,%5,%6,%7}, {%8,%9}, {%0,%1,%2,%3};"
        : "+f"(c[0]), "+f"(c[1]), "+f"(c[2]), "+f"(c[3])
        : "r"(a0), "r"(a1), "r"(a2), "r"(a3), "r"(b0), "r"(b1));
}

template <int NTILE>
__global__ __launch_bounds__(256, 2) void k_gemm(
    const __nv_bfloat16* __restrict__ Ah,
    const __nv_bfloat16* __restrict__ Al,
    const __nv_bfloat16* __restrict__ Bh,
    const __nv_bfloat16* __restrict__ Bl,
    unsigned short* __restrict__ Q,
    float* __restrict__ QS,
    int Ncol)
{
    constexpr int NT  = NTILE / 16;        // n-subtiles per warp (8 or 4)
    constexpr int BSZ = NTILE * 80;        // B tile bytes per buf per tensor
    constexpr int O_AH0 = 0, O_AH1 = 10240, O_AL0 = 20480, O_AL1 = 30720;
    constexpr int O_BH0 = 40960, O_BH1 = O_BH0 + BSZ;
    constexpr int O_BL0 = O_BH0 + 2 * BSZ, O_BL1 = O_BH0 + 3 * BSZ;

    extern __shared__ char sm[];
    const uint32_t sb = (uint32_t)__cvta_generic_to_shared(sm);

    int tid = threadIdx.x, wid = tid >> 5, lane = tid & 31;
    int g = lane >> 2, tig = lane & 3;
    int m0 = blockIdx.y * 128, n0 = blockIdx.x * NTILE;
    int wm = (wid >> 1) * 32;
    int wn = (wid & 1) * (NTILE / 2);

    int r0 = tid >> 2,         c0 = (tid & 3) * 8;
    int r1 = (tid + 256) >> 2, c1 = (tid & 3) * 8;

    const __nv_bfloat16* Ahb = Ah + (size_t)m0 * 512;
    const __nv_bfloat16* Alb = Al + (size_t)m0 * 512;
    const __nv_bfloat16* Bhb = Bh + (size_t)n0 * 512;
    const __nv_bfloat16* Blb = Bl + (size_t)n0 * 512;

    const uint32_t AHo[2] = {sb + O_AH0, sb + O_AH1};
    const uint32_t ALo[2] = {sb + O_AL0, sb + O_AL1};
    const uint32_t BHo[2] = {sb + O_BH0, sb + O_BH1};
    const uint32_t BLo[2] = {sb + O_BL0, sb + O_BL1};

    uint32_t a_base = (uint32_t)((wm + (lane & 7) + ((lane >> 3) & 1) * 8) * 80
                                 + ((lane >> 4) & 1) * 16);
    uint32_t b_base = (uint32_t)((wn + (lane & 7) + ((lane >> 4) & 1) * 8) * 80
                                 + ((lane >> 3) & 1) * 16);

    float acc[2][NT][4];
#pragma unroll
    for (int mt = 0; mt < 2; mt++)
#pragma unroll
        for (int nt = 0; nt < NT; nt++)
#pragma unroll
            for (int j = 0; j < 4; j++) acc[mt][nt][j] = 0.0f;

#define LOAD_CHUNK(buf, k0)                                                        \
    do {                                                                           \
        cp16(AHo[buf] + r0 * 80 + c0 * 2, Ahb + (size_t)r0 * 512 + (k0) + c0);     \
        cp16(AHo[buf] + r1 * 80 + c1 * 2, Ahb + (size_t)r1 * 512 + (k0) + c1);     \
        cp16(ALo[buf] + r0 * 80 + c0 * 2, Alb + (size_t)r0 * 512 + (k0) + c0);     \
        cp16(ALo[buf] + r1 * 80 + c1 * 2, Alb + (size_t)r1 * 512 + (k0) + c1);     \
        cp16(BHo[buf] + r0 * 80 + c0 * 2, Bhb + (size_t)r0 * 512 + (k0) + c0);     \
        cp16(BLo[buf] + r0 * 80 + c0 * 2, Blb + (size_t)r0 * 512 + (k0) + c0);     \
        if (NTILE == 128) {                                                        \
            cp16(BHo[buf] + r1 * 80 + c1 * 2, Bhb + (size_t)r1 * 512 + (k0) + c1); \
            cp16(BLo[buf] + r1 * 80 + c1 * 2, Blb + (size_t)r1 * 512 + (k0) + c1); \
        }                                                                          \
        cp_commit();                                                               \
    } while (0)

    LOAD_CHUNK(0, 0);

    for (int k = 0; k < 16; k++) {
        int buf = k & 1;
        cp_wait<0>();
        __syncthreads();
        if (k < 15) LOAD_CHUNK(buf ^ 1, (k + 1) * 32);

#pragma unroll
        for (int ks2 = 0; ks2 < 2; ks2++) {
            uint32_t ksb = ks2 * 32;
            uint32_t bhf[2 * NT], blf[2 * NT];
#pragma unroll
            for (int p = 0; p < NT / 2; p++) {
                ldsm4(bhf[4 * p], bhf[4 * p + 1], bhf[4 * p + 2], bhf[4 * p + 3],
                      BHo[buf] + b_base + p * 1280 + ksb);
                ldsm4(blf[4 * p], blf[4 * p + 1], blf[4 * p + 2], blf[4 * p + 3],
                      BLo[buf] + b_base + p * 1280 + ksb);
            }
#pragma unroll
            for (int mt = 0; mt < 2; mt++) {
                uint32_t ah0, ah1, ah2, ah3, al0, al1, al2, al3;
                ldsm4(ah0, ah1, ah2, ah3, AHo[buf] + a_base + mt * 1280 + ksb);
                ldsm4(al0, al1, al2, al3, ALo[buf] + a_base + mt * 1280 + ksb);
#pragma unroll
                for (int nt = 0; nt < NT; nt++) {
                    mma16816(acc[mt][nt], ah0, ah1, ah2, ah3, bhf[2 * nt], bhf[2 * nt + 1]);
                    mma16816(acc[mt][nt], ah0, ah1, ah2, ah3, blf[2 * nt], blf[2 * nt + 1]);
                    mma16816(acc[mt][nt], al0, al1, al2, al3, bhf[2 * nt], bhf[2 * nt + 1]);
                }
            }
        }
        __syncthreads();
    }

    // ---- epilogue: per-(row, CTA-col-block) scale -> int16 ----
    float* s_rm = (float*)sm;    // [128][2]

    float rmax[2][2];
#pragma unroll
    for (int mt = 0; mt < 2; mt++)
#pragma unroll
        for (int h = 0; h < 2; h++) {
            float m = 0.0f;
#pragma unroll
            for (int nt = 0; nt < NT; nt++)
                m = fmaxf(m, fmaxf(fabsf(acc[mt][nt][2 * h]), fabsf(acc[mt][nt][2 * h + 1])));
            m = fmaxf(m, __shfl_xor_sync(0xFFFFFFFFu, m, 1));
            m = fmaxf(m, __shfl_xor_sync(0xFFFFFFFFu, m, 2));
            rmax[mt][h] = m;
        }
    if (tig == 0) {
#pragma unroll
        for (int mt = 0; mt < 2; mt++)
#pragma unroll
            for (int h = 0; h < 2; h++)
                s_rm[(wm + mt * 16 + g + 8 * h) * 2 + (wid & 1)] = rmax[mt][h];
    }
    __syncthreads();

#pragma unroll
    for (int mt = 0; mt < 2; mt++)
#pragma unroll
        for (int h = 0; h < 2; h++) {
            int rl = wm + mt * 16 + g + 8 * h;
            float mx = fmaxf(s_rm[rl * 2 + 0], s_rm[rl * 2 + 1]);
            float inv = (mx > 0.0f) ? (32766.0f / mx) : 0.0f;
            if ((wid & 1) == 0 && tig == 0)
                QS[(size_t)(m0 + rl) * 4 + blockIdx.x] = mx * (1.0f / 32766.0f);
            size_t rowoff = (size_t)(m0 + rl) * Ncol + n0 + wn;
#pragma unroll
            for (int nt = 0; nt < NT; nt++) {
                uint32_t u0 = __float_as_uint(fmaf(acc[mt][nt][2 * h], inv, QMAGICF));
                uint32_t u1 = __float_as_uint(fmaf(acc[mt][nt][2 * h + 1], inv, QMAGICF));
                *(uint32_t*)&Q[rowoff + nt * 8 + tig * 2] = __byte_perm(u0, u1, 0x5410);
            }
        }
}

// ===========================================================================
// SpMM: int16 gather + exact per-element dequant.
// SHIFT maps thread -> scale block: nb = tid >> SHIFT.
// MODE 0: fp32 output; MODE 1: relu + bf16 (hi,lo) split output
// ===========================================================================
__device__ __forceinline__ void deq_fma(float4& a, float w, uint2 u) {
    uint32_t p0 = __byte_perm(u.x, 0x4B000000u, 0x7410);
    uint32_t p1 = __byte_perm(u.x, 0x4B000000u, 0x7432);
    uint32_t p2 = __byte_perm(u.y, 0x4B000000u, 0x7410);
    uint32_t p3 = __byte_perm(u.y, 0x4B000000u, 0x7432);
    a.x += w * (__uint_as_float(p0) - QMAGICF);
    a.y += w * (__uint_as_float(p1) - QMAGICF);
    a.z += w * (__uint_as_float(p2) - QMAGICF);
    a.w += w * (__uint_as_float(p3) - QMAGICF);
}

template <int NCOL, int NB, int MODE, int SHIFT>
__global__ __launch_bounds__(NCOL / 4) void k_spmm(const unsigned short* __restrict__ q,
                                                   const float* __restrict__ qs,
                                                   const float* __restrict__ bias,
                                                   float* __restrict__ outf,
                                                   __nv_bfloat16* __restrict__ oah,
                                                   __nv_bfloat16* __restrict__ oal) {
    constexpr int T = NCOL / 4;
    int row = blockIdx.x;
    int tid = threadIdx.x;

    __shared__ int   s_cols[MAXDEG];
    __shared__ float s_w[MAXDEG * NB];

    int n = g_cnt[row];
    for (int t = tid; t < n; t += T) {
        int j = g_cols[(size_t)row * MAXDEG + t];
        s_cols[t] = j;
        float dj = g_dinv[j];
#pragma unroll
        for (int b = 0; b < NB; b++) s_w[t * NB + b] = dj * qs[(size_t)j * 4 + b];
    }
    __syncthreads();

    int nb = tid >> SHIFT;
    const uint2* qp = (const uint2*)q;

    float4 acc = make_float4(0.0f, 0.0f, 0.0f, 0.0f);
    {
        float ws = g_selfcoef[row] * qs[(size_t)row * 4 + nb];
        deq_fma(acc, ws, qp[(size_t)row * T + tid]);
    }

    int t = 0;
    for (; t + 8 <= n; t += 8) {
        uint2 u[8];
        float w[8];
#pragma unroll
        for (int i = 0; i < 8; i++) {
            int j = s_cols[t + i];
            w[i] = s_w[(t + i) * NB + nb];
            u[i] = qp[(size_t)j * T + tid];
        }
#pragma unroll
        for (int i = 0; i < 8; i++) deq_fma(acc, w[i], u[i]);
    }
    for (; t < n; t++) {
        uint2 u = qp[(size_t)s_cols[t] * T + tid];
        deq_fma(acc, s_w[t * NB + nb], u);
    }

    float di = g_dinv[row];
    float4 bv = ((const float4*)bias)[tid];
    float4 r;
    r.x = di * acc.x + bv.x;
    r.y = di * acc.y + bv.y;
    r.z = di * acc.z + bv.z;
    r.w = di * acc.w + bv.w;

    if (MODE == 0) {
        ((float4*)outf)[(size_t)row * T + tid] = r;
    } else {
        r.x = fmaxf(r.x, 0.0f); r.y = fmaxf(r.y, 0.0f);
        r.z = fmaxf(r.z, 0.0f); r.w = fmaxf(r.w, 0.0f);
        float hx = __bfloat162float(__float2bfloat16_rn(r.x));
        float hy = __bfloat162float(__float2bfloat16_rn(r.y));
        float hz = __bfloat162float(__float2bfloat16_rn(r.z));
        float hw = __bfloat162float(__float2bfloat16_rn(r.w));
        ((uint2*)oah)[(size_t)row * T + tid] =
            make_uint2(packbf2(r.x, r.y), packbf2(r.z, r.w));
        ((uint2*)oal)[(size_t)row * T + tid] =
            make_uint2(packbf2(r.x - hx, r.y - hy), packbf2(r.z - hz, r.w - hw));
    }
}

// ===========================================================================
extern "C" void kernel_launch(void* const* d_in, const int* in_sizes, int n_in,
                              void* d_out, int out_size) {
    const float* x  = (const float*)d_in[0];
    const int*   ei = (const int*)d_in[1];
    const float* W1 = (const float*)d_in[2];
    const float* b1 = (const float*)d_in[3];
    const float* W2 = (const float*)d_in[4];
    const float* b2 = (const float*)d_in[5];
    const float* W3 = (const float*)d_in[6];
    const float* b3 = (const float*)d_in[7];
    float* out = (float*)d_out;

    int E = in_sizes[1] / 2;

    void *pah, *pal, *pbh, *pbl, *pq, *pqs;
    cudaGetSymbolAddress(&pah, g_ah);
    cudaGetSymbolAddress(&pal, g_al);
    cudaGetSymbolAddress(&pbh, g_bh);
    cudaGetSymbolAddress(&pbl, g_bl);
    cudaGetSymbolAddress(&pq, g_q);
    cudaGetSymbolAddress(&pqs, g_qs);
    __nv_bfloat16* ah = (__nv_bfloat16*)pah;
    __nv_bfloat16* al = (__nv_bfloat16*)pal;
    __nv_bfloat16* bh = (__nv_bfloat16*)pbh;
    __nv_bfloat16* bl = (__nv_bfloat16*)pbl;
    unsigned short* qb = (unsigned short*)pq;
    float* qsb = (float*)pqs;

    cudaFuncSetAttribute(k_gemm<128>, cudaFuncAttributeMaxDynamicSharedMemorySize, 81920);
    cudaFuncSetAttribute(k_gemm<64>,  cudaFuncAttributeMaxDynamicSharedMemorySize, 61440);

    // --- graph build + expansions ---
    k_clear_detect<<<2048, 256>>>(ei, E);
    k_scatter<<<(E + 255) / 256, 256>>>(ei, E);
    k_build_rows<<<NNODES / 8, 256>>>();
    k_expand_all<<<4096 + 2560, 256>>>(x, W1, W2, W3);

    dim3 g512(4, 64);     // 128x128 tiles
    dim3 g256(4, 64);     // 128x64 tiles for layer 3

    // layer 1
    k_gemm<128><<<g512, 256, 81920>>>(ah, al, bh, bl, qb, qsb, 512);
    k_spmm<512, 4, 1, 5><<<NNODES, 128>>>(qb, qsb, b1, nullptr, ah, al);

    // layer 2
    k_gemm<128><<<g512, 256, 81920>>>(ah, al, bh + 262144, bl + 262144, qb, qsb, 512);
    k_spmm<512, 4, 1, 5><<<NNODES, 128>>>(qb, qsb, b2, nullptr, ah, al);

    // layer 3 (128x64 tiles -> 256 CTAs, 2/SM)
    k_gemm<64><<<g256, 256, 61440>>>(ah, al, bh + 524288, bl + 524288, qb, qsb, 256);
    k_spmm<256, 4, 0, 4><<<NNODES, 64>>>(qb, qsb, b3, out, nullptr, nullptr);
}

// round 13
// speedup vs baseline: 1.0288x; 1.0288x over previous
#include <cuda_runtime.h>
#include <cuda_bf16.h>
#include <cstdint>

// ===========================================================================
// GCN: out = Anorm @ relu(Anorm @ relu(Anorm @ (x W1) + b1) W2 + b2) W3 + b3
// R12 base + stream-forked graph build (overlaps expand+GEMM1 in the graph).
// ===========================================================================

#define NNODES 8192
#define FDIM   512
#define WORDS_PER_ROW 256
#define MAXDEG 192
#define QMAGICF 8421376.0f    // 2^23 + 32768

__device__ unsigned int g_bits[NNODES * WORDS_PER_ROW];   // 8 MB
__device__ unsigned int g_self[WORDS_PER_ROW];
__device__ float g_dinv[NNODES];
__device__ float g_selfcoef[NNODES];
__device__ int   g_cols[NNODES * MAXDEG];
__device__ int   g_cnt[NNODES];
__device__ int   g_is64;
__device__ __nv_bfloat16 g_ah[NNODES * FDIM];             // 8 MB activation hi
__device__ __nv_bfloat16 g_al[NNODES * FDIM];             // 8 MB activation lo
__device__ __nv_bfloat16 g_bh[655360];                    // W1|W2|W3 hi, n-major
__device__ __nv_bfloat16 g_bl[655360];                    // W1|W2|W3 lo
__device__ unsigned short g_q[NNODES * FDIM];             // quantized GEMM out
__device__ float g_qs[NNODES * 4];                        // per-(row, col-block) scale

// ===========================================================================
// K0: clear bit matrix (uint4 stores) + int64 detect
// ===========================================================================
__global__ void k_clear_detect(const int* __restrict__ ei, int E) {
    int i4 = blockIdx.x * blockDim.x + threadIdx.x;   // [0, 524288)
    if (i4 == 0) g_is64 = 1;
    int row = i4 >> 6;
    int lw  = (i4 & 63) * 4;
    int dw  = row >> 5;
    uint4 v = make_uint4(0u, 0u, 0u, 0u);
    if (dw >= lw && dw < lw + 4)
        ((unsigned*)&v)[dw - lw] = 1u << (row & 31);
    ((uint4*)g_bits)[i4] = v;
    if (i4 < 64) ((uint4*)g_self)[i4] = make_uint4(0u, 0u, 0u, 0u);
    if (i4 < E) {
        if (ei[2 * i4 + 1] != 0) g_is64 = 0;
    }
}

// ===========================================================================
// K1: scatter edges (set semantics)
// ===========================================================================
__global__ void k_scatter(const int* __restrict__ w, int E) {
    int i = blockIdx.x * blockDim.x + threadIdx.x;
    if (i >= E) return;
    int a, b;
    if (g_is64) { a = w[2 * i]; b = w[2 * E + 2 * i]; }
    else        { a = w[i];     b = w[E + i]; }
    if ((unsigned)a >= NNODES || (unsigned)b >= NNODES) return;
    atomicOr(&g_bits[(size_t)a * WORDS_PER_ROW + (b >> 5)], 1u << (b & 31));
    atomicOr(&g_bits[(size_t)b * WORDS_PER_ROW + (a >> 5)], 1u << (a & 31));
    if (a == b) atomicOr(&g_self[a >> 5], 1u << (a & 31));
}

// ===========================================================================
// K2: per-row compaction + degree normalization (uint4 row loads)
// ===========================================================================
__global__ void k_build_rows() {
    int warp = (blockIdx.x * blockDim.x + threadIdx.x) >> 5;
    int lane = threadIdx.x & 31;
    if (warp >= NNODES) return;
    int row = warp;

    const uint4* b4 = (const uint4*)&g_bits[(size_t)row * WORDS_PER_ROW];
    uint4 u0 = b4[lane * 2];
    uint4 u1 = b4[lane * 2 + 1];
    unsigned int w[8] = {u0.x, u0.y, u0.z, u0.w, u1.x, u1.y, u1.z, u1.w};

    int dw = row >> 5;
    if ((dw >> 3) == lane) w[dw & 7] &= ~(1u << (row & 31));

    unsigned int cnt = 0;
#pragma unroll
    for (int t = 0; t < 8; t++) cnt += __popc(w[t]);

    unsigned int incl = cnt;
#pragma unroll
    for (int d = 1; d < 32; d <<= 1) {
        unsigned int v = __shfl_up_sync(0xFFFFFFFFu, incl, d);
        if (lane >= d) incl += v;
    }
    unsigned int excl  = incl - cnt;
    unsigned int total = __shfl_sync(0xFFFFFFFFu, incl, 31);

    int* cols = &g_cols[(size_t)row * MAXDEG];
    unsigned int o = excl;
#pragma unroll
    for (int t = 0; t < 8; t++) {
        unsigned int bits = w[t];
        int colbase = (lane * 8 + t) * 32;
        while (bits) {
            int b = __ffs(bits) - 1;
            bits &= bits - 1;
            if (o < MAXDEG) cols[o] = colbase + b;
            o++;
        }
    }

    if (lane == 0) {
        int self = (g_self[row >> 5] >> (row & 31)) & 1;
        float deg = (float)total + 1.0f + (float)self;
        float di = rsqrtf(deg);
        g_dinv[row] = di;
        g_selfcoef[row] = (1.0f + (float)self) * di;
        g_cnt[row] = (int)(total < MAXDEG ? total : MAXDEG);
    }
}

// ===========================================================================
// K3: expandX + expandB (one kernel, disjoint block ranges)
// ===========================================================================
__device__ __forceinline__ uint32_t packbf2(float x, float y) {
    __nv_bfloat162 t = __floats2bfloat162_rn(x, y);
    return *(uint32_t*)&t;
}

__global__ void k_expand_all(const float* __restrict__ X,
                             const float* __restrict__ W1,
                             const float* __restrict__ W2,
                             const float* __restrict__ W3) {
    int bid = blockIdx.x;
    if (bid < 4096) {
        int idx = bid * 256 + threadIdx.x;
        float4 v = ((const float4*)X)[idx];
        float hx = __bfloat162float(__float2bfloat16_rn(v.x));
        float hy = __bfloat162float(__float2bfloat16_rn(v.y));
        float hz = __bfloat162float(__float2bfloat16_rn(v.z));
        float hw = __bfloat162float(__float2bfloat16_rn(v.w));
        ((uint2*)g_ah)[idx] = make_uint2(packbf2(v.x, v.y), packbf2(v.z, v.w));
        ((uint2*)g_al)[idx] = make_uint2(packbf2(v.x - hx, v.y - hy),
                                         packbf2(v.z - hz, v.w - hw));
    } else {
        int idx = (bid - 4096) * 256 + threadIdx.x;
        if (idx >= 655360) return;
        const float* W;
        int Ncol, local;
        if (idx < 262144)      { W = W1; Ncol = 512; local = idx; }
        else if (idx < 524288) { W = W2; Ncol = 512; local = idx - 262144; }
        else                   { W = W3; Ncol = 256; local = idx - 524288; }
        int n = local >> 9;
        int k = local & 511;
        float v = W[(size_t)k * Ncol + n];
        __nv_bfloat16 hi = __float2bfloat16_rn(v);
        __nv_bfloat16 lo = __float2bfloat16_rn(v - __bfloat162float(hi));
        g_bh[idx] = hi;
        g_bl[idx] = lo;
    }
}

// ===========================================================================
// GEMM: C = A @ W via ah*bh + ah*bl + al*bh. 2 CTAs/SM, single-sync pipeline.
// ===========================================================================
__device__ __forceinline__ void cp16(uint32_t saddr, const void* g) {
    asm volatile("cp.async.cg.shared.global [%0], [%1], 16;" :: "r"(saddr), "l"(g));
}
__device__ __forceinline__ void cp_commit() { asm volatile("cp.async.commit_group;"); }
template <int N> __device__ __forceinline__ void cp_wait() {
    asm volatile("cp.async.wait_group %0;" :: "n"(N));
}
__device__ __forceinline__ void ldsm4(uint32_t& r0, uint32_t& r1, uint32_t& r2,
                                      uint32_t& r3, uint32_t addr) {
    asm volatile("ldmatrix.sync.aligned.m8n8.x4.shared.b16 {%0,%1,%2,%3}, [%4];"
                 : "=r"(r0), "=r"(r1), "=r"(r2), "=r"(r3) : "r"(addr));
}
__device__ __forceinline__ void mma16816(float* c, uint32_t a0, uint32_t a1,
                                         uint32_t a2, uint32_t a3,
                                         uint32_t b0, uint32_t b1) {
    asm volatile(
        "mma.sync.aligned.m16n8k16.row.col.f32.bf16.bf16.f32 "
        "{%0,%1,%2,%3}, {%4,%5,%6,%7}, {%8,%9}, {%0,%1,%2,%3};"
        : "+f"(c[0]), "+f"(c[1]), "+f"(c[2]), "+f"(c[3])
        : "r"(a0), "r"(a1), "r"(a2), "r"(a3), "r"(b0), "r"(b1));
}

template <int NTILE>
__global__ __launch_bounds__(256, 2) void k_gemm(
    const __nv_bfloat16* __restrict__ Ah,
    const __nv_bfloat16* __restrict__ Al,
    const __nv_bfloat16* __restrict__ Bh,
    const __nv_bfloat16* __restrict__ Bl,
    unsigned short* __restrict__ Q,
    float* __restrict__ QS,
    int Ncol)
{
    constexpr int NT  = NTILE / 16;
    constexpr int BSZ = NTILE * 80;
    constexpr int O_AH0 = 0, O_AH1 = 10240, O_AL0 = 20480, O_AL1 = 30720;
    constexpr int O_BH0 = 40960, O_BH1 = O_BH0 + BSZ;
    constexpr int O_BL0 = O_BH0 + 2 * BSZ, O_BL1 = O_BH0 + 3 * BSZ;

    extern __shared__ char sm[];
    const uint32_t sb = (uint32_t)__cvta_generic_to_shared(sm);

    int tid = threadIdx.x, wid = tid >> 5, lane = tid & 31;
    int g = lane >> 2, tig = lane & 3;
    int m0 = blockIdx.y * 128, n0 = blockIdx.x * NTILE;
    int wm = (wid >> 1) * 32;
    int wn = (wid & 1) * (NTILE / 2);

    int r0 = tid >> 2,         c0 = (tid & 3) * 8;
    int r1 = (tid + 256) >> 2, c1 = (tid & 3) * 8;

    const __nv_bfloat16* Ahb = Ah + (size_t)m0 * 512;
    const __nv_bfloat16* Alb = Al + (size_t)m0 * 512;
    const __nv_bfloat16* Bhb = Bh + (size_t)n0 * 512;
    const __nv_bfloat16* Blb = Bl + (size_t)n0 * 512;

    const uint32_t AHo[2] = {sb + O_AH0, sb + O_AH1};
    const uint32_t ALo[2] = {sb + O_AL0, sb + O_AL1};
    const uint32_t BHo[2] = {sb + O_BH0, sb + O_BH1};
    const uint32_t BLo[2] = {sb + O_BL0, sb + O_BL1};

    uint32_t a_base = (uint32_t)((wm + (lane & 7) + ((lane >> 3) & 1) * 8) * 80
                                 + ((lane >> 4) & 1) * 16);
    uint32_t b_base = (uint32_t)((wn + (lane & 7) + ((lane >> 4) & 1) * 8) * 80
                                 + ((lane >> 3) & 1) * 16);

    float acc[2][NT][4];
#pragma unroll
    for (int mt = 0; mt < 2; mt++)
#pragma unroll
        for (int nt = 0; nt < NT; nt++)
#pragma unroll
            for (int j = 0; j < 4; j++) acc[mt][nt][j] = 0.0f;

#define LOAD_CHUNK(buf, k0)                                                        \
    do {                                                                           \
        cp16(AHo[buf] + r0 * 80 + c0 * 2, Ahb + (size_t)r0 * 512 + (k0) + c0);     \
        cp16(AHo[buf] + r1 * 80 + c1 * 2, Ahb + (size_t)r1 * 512 + (k0) + c1);     \
        cp16(ALo[buf] + r0 * 80 + c0 * 2, Alb + (size_t)r0 * 512 + (k0) + c0);     \
        cp16(ALo[buf] + r1 * 80 + c1 * 2, Alb + (size_t)r1 * 512 + (k0) + c1);     \
        cp16(BHo[buf] + r0 * 80 + c0 * 2, Bhb + (size_t)r0 * 512 + (k0) + c0);     \
        cp16(BLo[buf] + r0 * 80 + c0 * 2, Blb + (size_t)r0 * 512 + (k0) + c0);     \
        if (NTILE == 128) {                                                        \
            cp16(BHo[buf] + r1 * 80 + c1 * 2, Bhb + (size_t)r1 * 512 + (k0) + c1); \
            cp16(BLo[buf] + r1 * 80 + c1 * 2, Blb + (size_t)r1 * 512 + (k0) + c1); \
        }                                                                          \
        cp_commit();                                                               \
    } while (0)

    LOAD_CHUNK(0, 0);

    for (int k = 0; k < 16; k++) {
        int buf = k & 1;
        cp_wait<0>();
        __syncthreads();
        if (k < 15) LOAD_CHUNK(buf ^ 1, (k + 1) * 32);

#pragma unroll
        for (int ks2 = 0; ks2 < 2; ks2++) {
            uint32_t ksb = ks2 * 32;
            uint32_t bhf[2 * NT], blf[2 * NT];
#pragma unroll
            for (int p = 0; p < NT / 2; p++) {
                ldsm4(bhf[4 * p], bhf[4 * p + 1], bhf[4 * p + 2], bhf[4 * p + 3],
                      BHo[buf] + b_base + p * 1280 + ksb);
                ldsm4(blf[4 * p], blf[4 * p + 1], blf[4 * p + 2], blf[4 * p + 3],
                      BLo[buf] + b_base + p * 1280 + ksb);
            }
#pragma unroll
            for (int mt = 0; mt < 2; mt++) {
                uint32_t ah0, ah1, ah2, ah3, al0, al1, al2, al3;
                ldsm4(ah0, ah1, ah2, ah3, AHo[buf] + a_base + mt * 1280 + ksb);
                ldsm4(al0, al1, al2, al3, ALo[buf] + a_base + mt * 1280 + ksb);
#pragma unroll
                for (int nt = 0; nt < NT; nt++) {
                    mma16816(acc[mt][nt], ah0, ah1, ah2, ah3, bhf[2 * nt], bhf[2 * nt + 1]);
                    mma16816(acc[mt][nt], ah0, ah1, ah2, ah3, blf[2 * nt], blf[2 * nt + 1]);
                    mma16816(acc[mt][nt], al0, al1, al2, al3, bhf[2 * nt], bhf[2 * nt + 1]);
                }
            }
        }
        __syncthreads();
    }

    // ---- epilogue: per-(row, CTA-col-block) scale -> int16 ----
    float* s_rm = (float*)sm;

    float rmax[2][2];
#pragma unroll
    for (int mt = 0; mt < 2; mt++)
#pragma unroll
        for (int h = 0; h < 2; h++) {
            float m = 0.0f;
#pragma unroll
            for (int nt = 0; nt < NT; nt++)
                m = fmaxf(m, fmaxf(fabsf(acc[mt][nt][2 * h]), fabsf(acc[mt][nt][2 * h + 1])));
            m = fmaxf(m, __shfl_xor_sync(0xFFFFFFFFu, m, 1));
            m = fmaxf(m, __shfl_xor_sync(0xFFFFFFFFu, m, 2));
            rmax[mt][h] = m;
        }
    if (tig == 0) {
#pragma unroll
        for (int mt = 0; mt < 2; mt++)
#pragma unroll
            for (int h = 0; h < 2; h++)
                s_rm[(wm + mt * 16 + g + 8 * h) * 2 + (wid & 1)] = rmax[mt][h];
    }
    __syncthreads();

#pragma unroll
    for (int mt = 0; mt < 2; mt++)
#pragma unroll
        for (int h = 0; h < 2; h++) {
            int rl = wm + mt * 16 + g + 8 * h;
            float mx = fmaxf(s_rm[rl * 2 + 0], s_rm[rl * 2 + 1]);
            float inv = (mx > 0.0f) ? (32766.0f / mx) : 0.0f;
            if ((wid & 1) == 0 && tig == 0)
                QS[(size_t)(m0 + rl) * 4 + blockIdx.x] = mx * (1.0f / 32766.0f);
            size_t rowoff = (size_t)(m0 + rl) * Ncol + n0 + wn;
#pragma unroll
            for (int nt = 0; nt < NT; nt++) {
                uint32_t u0 = __float_as_uint(fmaf(acc[mt][nt][2 * h], inv, QMAGICF));
                uint32_t u1 = __float_as_uint(fmaf(acc[mt][nt][2 * h + 1], inv, QMAGICF));
                *(uint32_t*)&Q[rowoff + nt * 8 + tig * 2] = __byte_perm(u0, u1, 0x5410);
            }
        }
}

// ===========================================================================
// SpMM: int16 gather + exact per-element dequant.
// ===========================================================================
__device__ __forceinline__ void deq_fma(float4& a, float w, uint2 u) {
    uint32_t p0 = __byte_perm(u.x, 0x4B000000u, 0x7410);
    uint32_t p1 = __byte_perm(u.x, 0x4B000000u, 0x7432);
    uint32_t p2 = __byte_perm(u.y, 0x4B000000u, 0x7410);
    uint32_t p3 = __byte_perm(u.y, 0x4B000000u, 0x7432);
    a.x += w * (__uint_as_float(p0) - QMAGICF);
    a.y += w * (__uint_as_float(p1) - QMAGICF);
    a.z += w * (__uint_as_float(p2) - QMAGICF);
    a.w += w * (__uint_as_float(p3) - QMAGICF);
}

template <int NCOL, int NB, int MODE, int SHIFT>
__global__ __launch_bounds__(NCOL / 4) void k_spmm(const unsigned short* __restrict__ q,
                                                   const float* __restrict__ qs,
                                                   const float* __restrict__ bias,
                                                   float* __restrict__ outf,
                                                   __nv_bfloat16* __restrict__ oah,
                                                   __nv_bfloat16* __restrict__ oal) {
    constexpr int T = NCOL / 4;
    int row = blockIdx.x;
    int tid = threadIdx.x;

    __shared__ int   s_cols[MAXDEG];
    __shared__ float s_w[MAXDEG * NB];

    int n = g_cnt[row];
    for (int t = tid; t < n; t += T) {
        int j = g_cols[(size_t)row * MAXDEG + t];
        s_cols[t] = j;
        float dj = g_dinv[j];
#pragma unroll
        for (int b = 0; b < NB; b++) s_w[t * NB + b] = dj * qs[(size_t)j * 4 + b];
    }
    __syncthreads();

    int nb = tid >> SHIFT;
    const uint2* qp = (const uint2*)q;

    float4 acc = make_float4(0.0f, 0.0f, 0.0f, 0.0f);
    {
        float ws = g_selfcoef[row] * qs[(size_t)row * 4 + nb];
        deq_fma(acc, ws, qp[(size_t)row * T + tid]);
    }

    int t = 0;
    for (; t + 8 <= n; t += 8) {
        uint2 u[8];
        float w[8];
#pragma unroll
        for (int i = 0; i < 8; i++) {
            int j = s_cols[t + i];
            w[i] = s_w[(t + i) * NB + nb];
            u[i] = qp[(size_t)j * T + tid];
        }
#pragma unroll
        for (int i = 0; i < 8; i++) deq_fma(acc, w[i], u[i]);
    }
    for (; t < n; t++) {
        uint2 u = qp[(size_t)s_cols[t] * T + tid];
        deq_fma(acc, s_w[t * NB + nb], u);
    }

    float di = g_dinv[row];
    float4 bv = ((const float4*)bias)[tid];
    float4 r;
    r.x = di * acc.x + bv.x;
    r.y = di * acc.y + bv.y;
    r.z = di * acc.z + bv.z;
    r.w = di * acc.w + bv.w;

    if (MODE == 0) {
        ((float4*)outf)[(size_t)row * T + tid] = r;
    } else {
        r.x = fmaxf(r.x, 0.0f); r.y = fmaxf(r.y, 0.0f);
        r.z = fmaxf(r.z, 0.0f); r.w = fmaxf(r.w, 0.0f);
        float hx = __bfloat162float(__float2bfloat16_rn(r.x));
        float hy = __bfloat162float(__float2bfloat16_rn(r.y));
        float hz = __bfloat162float(__float2bfloat16_rn(r.z));
        float hw = __bfloat162float(__float2bfloat16_rn(r.w));
        ((uint2*)oah)[(size_t)row * T + tid] =
            make_uint2(packbf2(r.x, r.y), packbf2(r.z, r.w));
        ((uint2*)oal)[(size_t)row * T + tid] =
            make_uint2(packbf2(r.x - hx, r.y - hy), packbf2(r.z - hz, r.w - hw));
    }
}

// ===========================================================================
extern "C" void kernel_launch(void* const* d_in, const int* in_sizes, int n_in,
                              void* d_out, int out_size) {
    const float* x  = (const float*)d_in[0];
    const int*   ei = (const int*)d_in[1];
    const float* W1 = (const float*)d_in[2];
    const float* b1 = (const float*)d_in[3];
    const float* W2 = (const float*)d_in[4];
    const float* b2 = (const float*)d_in[5];
    const float* W3 = (const float*)d_in[6];
    const float* b3 = (const float*)d_in[7];
    float* out = (float*)d_out;

    int E = in_sizes[1] / 2;

    void *pah, *pal, *pbh, *pbl, *pq, *pqs;
    cudaGetSymbolAddress(&pah, g_ah);
    cudaGetSymbolAddress(&pal, g_al);
    cudaGetSymbolAddress(&pbh, g_bh);
    cudaGetSymbolAddress(&pbl, g_bl);
    cudaGetSymbolAddress(&pq, g_q);
    cudaGetSymbolAddress(&pqs, g_qs);
    __nv_bfloat16* ah = (__nv_bfloat16*)pah;
    __nv_bfloat16* al = (__nv_bfloat16*)pal;
    __nv_bfloat16* bh = (__nv_bfloat16*)pbh;
    __nv_bfloat16* bl = (__nv_bfloat16*)pbl;
    unsigned short* qb = (unsigned short*)pq;
    float* qsb = (float*)pqs;

    cudaFuncSetAttribute(k_gemm<128>, cudaFuncAttributeMaxDynamicSharedMemorySize, 81920);
    cudaFuncSetAttribute(k_gemm<64>,  cudaFuncAttributeMaxDynamicSharedMemorySize, 61440);

    // --- fork: graph build runs concurrently with expand + GEMM1 ---
    cudaStream_t s1;
    cudaEvent_t evFork, evJoin;
    cudaStreamCreateWithFlags(&s1, cudaStreamNonBlocking);
    cudaEventCreateWithFlags(&evFork, cudaEventDisableTiming);
    cudaEventCreateWithFlags(&evJoin, cudaEventDisableTiming);

    cudaEventRecord(evFork, 0);
    cudaStreamWaitEvent(s1, evFork, 0);
    k_clear_detect<<<2048, 256, 0, s1>>>(ei, E);
    k_scatter<<<(E + 255) / 256, 256, 0, s1>>>(ei, E);
    k_build_rows<<<NNODES / 8, 256, 0, s1>>>();
    cudaEventRecord(evJoin, s1);

    // main stream: expand + GEMM1 (independent of graph build)
    k_expand_all<<<4096 + 2560, 256>>>(x, W1, W2, W3);

    dim3 g512(4, 64);
    dim3 g256(4, 64);

    k_gemm<128><<<g512, 256, 81920>>>(ah, al, bh, bl, qb, qsb, 512);

    // join: SpMM1 needs the graph structure
    cudaStreamWaitEvent(0, evJoin, 0);
    k_spmm<512, 4, 1, 5><<<NNODES, 128>>>(qb, qsb, b1, nullptr, ah, al);

    // layer 2
    k_gemm<128><<<g512, 256, 81920>>>(ah, al, bh + 262144, bl + 262144, qb, qsb, 512);
    k_spmm<512, 4, 1, 5><<<NNODES, 128>>>(qb, qsb, b2, nullptr, ah, al);

    // layer 3 (128x64 tiles -> 256 CTAs, 2/SM)
    k_gemm<64><<<g256, 256, 61440>>>(ah, al, bh + 524288, bl + 524288, qb, qsb, 256);
    k_spmm<256, 4, 0, 4><<<NNODES, 64>>>(qb, qsb, b3, out, nullptr, nullptr);
}

// round 14
// speedup vs baseline: 1.0293x; 1.0005x over previous
#include <cuda_runtime.h>
#include <cuda_bf16.h>
#include <cstdint>

// ===========================================================================
// GCN: out = Anorm @ relu(Anorm @ relu(Anorm @ (x W1) + b1) W2 + b2) W3 + b3
// R13 base + expand split: X/W1 on critical path, W2/W3 hidden on side stream
// behind the graph-build chain (all overlapped with GEMM1).
// ===========================================================================

#define NNODES 8192
#define FDIM   512
#define WORDS_PER_ROW 256
#define MAXDEG 192
#define QMAGICF 8421376.0f    // 2^23 + 32768

__device__ unsigned int g_bits[NNODES * WORDS_PER_ROW];   // 8 MB
__device__ unsigned int g_self[WORDS_PER_ROW];
__device__ float g_dinv[NNODES];
__device__ float g_selfcoef[NNODES];
__device__ int   g_cols[NNODES * MAXDEG];
__device__ int   g_cnt[NNODES];
__device__ int   g_is64;
__device__ __nv_bfloat16 g_ah[NNODES * FDIM];             // 8 MB activation hi
__device__ __nv_bfloat16 g_al[NNODES * FDIM];             // 8 MB activation lo
__device__ __nv_bfloat16 g_bh[655360];                    // W1|W2|W3 hi, n-major
__device__ __nv_bfloat16 g_bl[655360];                    // W1|W2|W3 lo
__device__ unsigned short g_q[NNODES * FDIM];             // quantized GEMM out
__device__ float g_qs[NNODES * 4];                        // per-(row, col-block) scale

// ===========================================================================
// K0: clear bit matrix (uint4 stores) + int64 detect
// ===========================================================================
__global__ void k_clear_detect(const int* __restrict__ ei, int E) {
    int i4 = blockIdx.x * blockDim.x + threadIdx.x;   // [0, 524288)
    if (i4 == 0) g_is64 = 1;
    int row = i4 >> 6;
    int lw  = (i4 & 63) * 4;
    int dw  = row >> 5;
    uint4 v = make_uint4(0u, 0u, 0u, 0u);
    if (dw >= lw && dw < lw + 4)
        ((unsigned*)&v)[dw - lw] = 1u << (row & 31);
    ((uint4*)g_bits)[i4] = v;
    if (i4 < 64) ((uint4*)g_self)[i4] = make_uint4(0u, 0u, 0u, 0u);
    if (i4 < E) {
        if (ei[2 * i4 + 1] != 0) g_is64 = 0;
    }
}

// ===========================================================================
// K1: scatter edges (set semantics)
// ===========================================================================
__global__ void k_scatter(const int* __restrict__ w, int E) {
    int i = blockIdx.x * blockDim.x + threadIdx.x;
    if (i >= E) return;
    int a, b;
    if (g_is64) { a = w[2 * i]; b = w[2 * E + 2 * i]; }
    else        { a = w[i];     b = w[E + i]; }
    if ((unsigned)a >= NNODES || (unsigned)b >= NNODES) return;
    atomicOr(&g_bits[(size_t)a * WORDS_PER_ROW + (b >> 5)], 1u << (b & 31));
    atomicOr(&g_bits[(size_t)b * WORDS_PER_ROW + (a >> 5)], 1u << (a & 31));
    if (a == b) atomicOr(&g_self[a >> 5], 1u << (a & 31));
}

// ===========================================================================
// K2: per-row compaction + degree normalization (uint4 row loads)
// ===========================================================================
__global__ void k_build_rows() {
    int warp = (blockIdx.x * blockDim.x + threadIdx.x) >> 5;
    int lane = threadIdx.x & 31;
    if (warp >= NNODES) return;
    int row = warp;

    const uint4* b4 = (const uint4*)&g_bits[(size_t)row * WORDS_PER_ROW];
    uint4 u0 = b4[lane * 2];
    uint4 u1 = b4[lane * 2 + 1];
    unsigned int w[8] = {u0.x, u0.y, u0.z, u0.w, u1.x, u1.y, u1.z, u1.w};

    int dw = row >> 5;
    if ((dw >> 3) == lane) w[dw & 7] &= ~(1u << (row & 31));

    unsigned int cnt = 0;
#pragma unroll
    for (int t = 0; t < 8; t++) cnt += __popc(w[t]);

    unsigned int incl = cnt;
#pragma unroll
    for (int d = 1; d < 32; d <<= 1) {
        unsigned int v = __shfl_up_sync(0xFFFFFFFFu, incl, d);
        if (lane >= d) incl += v;
    }
    unsigned int excl  = incl - cnt;
    unsigned int total = __shfl_sync(0xFFFFFFFFu, incl, 31);

    int* cols = &g_cols[(size_t)row * MAXDEG];
    unsigned int o = excl;
#pragma unroll
    for (int t = 0; t < 8; t++) {
        unsigned int bits = w[t];
        int colbase = (lane * 8 + t) * 32;
        while (bits) {
            int b = __ffs(bits) - 1;
            bits &= bits - 1;
            if (o < MAXDEG) cols[o] = colbase + b;
            o++;
        }
    }

    if (lane == 0) {
        int self = (g_self[row >> 5] >> (row & 31)) & 1;
        float deg = (float)total + 1.0f + (float)self;
        float di = rsqrtf(deg);
        g_dinv[row] = di;
        g_selfcoef[row] = (1.0f + (float)self) * di;
        g_cnt[row] = (int)(total < MAXDEG ? total : MAXDEG);
    }
}

// ===========================================================================
// Expansion helpers
// ===========================================================================
__device__ __forceinline__ uint32_t packbf2(float x, float y) {
    __nv_bfloat162 t = __floats2bfloat162_rn(x, y);
    return *(uint32_t*)&t;
}

__device__ __forceinline__ void expandW(const float* __restrict__ W, int Ncol,
                                        int local, int gofs) {
    int n = local >> 9;
    int k = local & 511;
    float v = W[(size_t)k * Ncol + n];
    __nv_bfloat16 hi = __float2bfloat16_rn(v);
    __nv_bfloat16 lo = __float2bfloat16_rn(v - __bfloat162float(hi));
    g_bh[gofs + local] = hi;
    g_bl[gofs + local] = lo;
}

// K3a: expand X + W1 (critical path for GEMM1)
__global__ void k_expand1(const float* __restrict__ X, const float* __restrict__ W1) {
    int bid = blockIdx.x;
    if (bid < 4096) {
        int idx = bid * 256 + threadIdx.x;           // over (8192*512)/4
        float4 v = ((const float4*)X)[idx];
        float hx = __bfloat162float(__float2bfloat16_rn(v.x));
        float hy = __bfloat162float(__float2bfloat16_rn(v.y));
        float hz = __bfloat162float(__float2bfloat16_rn(v.z));
        float hw = __bfloat162float(__float2bfloat16_rn(v.w));
        ((uint2*)g_ah)[idx] = make_uint2(packbf2(v.x, v.y), packbf2(v.z, v.w));
        ((uint2*)g_al)[idx] = make_uint2(packbf2(v.x - hx, v.y - hy),
                                         packbf2(v.z - hz, v.w - hw));
    } else {
        int idx = (bid - 4096) * 256 + threadIdx.x;  // over 262144 (W1)
        expandW(W1, 512, idx, 0);
    }
}

// K3b: expand W2 + W3 (hidden on side stream)
__global__ void k_expand23(const float* __restrict__ W2, const float* __restrict__ W3) {
    int idx = blockIdx.x * 256 + threadIdx.x;        // over 393216
    if (idx < 262144) expandW(W2, 512, idx, 262144);
    else if (idx < 393216) expandW(W3, 256, idx - 262144, 524288);
}

// ===========================================================================
// GEMM: C = A @ W via ah*bh + ah*bl + al*bh. 2 CTAs/SM, single-sync pipeline.
// ===========================================================================
__device__ __forceinline__ void cp16(uint32_t saddr, const void* g) {
    asm volatile("cp.async.cg.shared.global [%0], [%1], 16;" :: "r"(saddr), "l"(g));
}
__device__ __forceinline__ void cp_commit() { asm volatile("cp.async.commit_group;"); }
template <int N> __device__ __forceinline__ void cp_wait() {
    asm volatile("cp.async.wait_group %0;" :: "n"(N));
}
__device__ __forceinline__ void ldsm4(uint32_t& r0, uint32_t& r1, uint32_t& r2,
                                      uint32_t& r3, uint32_t addr) {
    asm volatile("ldmatrix.sync.aligned.m8n8.x4.shared.b16 {%0,%1,%2,%3}, [%4];"
                 : "=r"(r0), "=r"(r1), "=r"(r2), "=r"(r3) : "r"(addr));
}
__device__ __forceinline__ void mma16816(float* c, uint32_t a0, uint32_t a1,
                                         uint32_t a2, uint32_t a3,
                                         uint32_t b0, uint32_t b1) {
    asm volatile(
        "mma.sync.aligned.m16n8k16.row.col.f32.bf16.bf16.f32 "
        "{%0,%1,%2,%3}, {%4,%5,%6,%7}, {%8,%9}, {%0,%1,%2,%3};"
        : "+f"(c[0]), "+f"(c[1]), "+f"(c[2]), "+f"(c[3])
        : "r"(a0), "r"(a1), "r"(a2), "r"(a3), "r"(b0), "r"(b1));
}

template <int NTILE>
__global__ __launch_bounds__(256, 2) void k_gemm(
    const __nv_bfloat16* __restrict__ Ah,
    const __nv_bfloat16* __restrict__ Al,
    const __nv_bfloat16* __restrict__ Bh,
    const __nv_bfloat16* __restrict__ Bl,
    unsigned short* __restrict__ Q,
    float* __restrict__ QS,
    int Ncol)
{
    constexpr int NT  = NTILE / 16;
    constexpr int BSZ = NTILE * 80;
    constexpr int O_AH0 = 0, O_AH1 = 10240, O_AL0 = 20480, O_AL1 = 30720;
    constexpr int O_BH0 = 40960, O_BH1 = O_BH0 + BSZ;
    constexpr int O_BL0 = O_BH0 + 2 * BSZ, O_BL1 = O_BH0 + 3 * BSZ;

    extern __shared__ char sm[];
    const uint32_t sb = (uint32_t)__cvta_generic_to_shared(sm);

    int tid = threadIdx.x, wid = tid >> 5, lane = tid & 31;
    int g = lane >> 2, tig = lane & 3;
    int m0 = blockIdx.y * 128, n0 = blockIdx.x * NTILE;
    int wm = (wid >> 1) * 32;
    int wn = (wid & 1) * (NTILE / 2);

    int r0 = tid >> 2,         c0 = (tid & 3) * 8;
    int r1 = (tid + 256) >> 2, c1 = (tid & 3) * 8;

    const __nv_bfloat16* Ahb = Ah + (size_t)m0 * 512;
    const __nv_bfloat16* Alb = Al + (size_t)m0 * 512;
    const __nv_bfloat16* Bhb = Bh + (size_t)n0 * 512;
    const __nv_bfloat16* Blb = Bl + (size_t)n0 * 512;

    const uint32_t AHo[2] = {sb + O_AH0, sb + O_AH1};
    const uint32_t ALo[2] = {sb + O_AL0, sb + O_AL1};
    const uint32_t BHo[2] = {sb + O_BH0, sb + O_BH1};
    const uint32_t BLo[2] = {sb + O_BL0, sb + O_BL1};

    uint32_t a_base = (uint32_t)((wm + (lane & 7) + ((lane >> 3) & 1) * 8) * 80
                                 + ((lane >> 4) & 1) * 16);
    uint32_t b_base = (uint32_t)((wn + (lane & 7) + ((lane >> 4) & 1) * 8) * 80
                                 + ((lane >> 3) & 1) * 16);

    float acc[2][NT][4];
#pragma unroll
    for (int mt = 0; mt < 2; mt++)
#pragma unroll
        for (int nt = 0; nt < NT; nt++)
#pragma unroll
            for (int j = 0; j < 4; j++) acc[mt][nt][j] = 0.0f;

#define LOAD_CHUNK(buf, k0)                                                        \
    do {                                                                           \
        cp16(AHo[buf] + r0 * 80 + c0 * 2, Ahb + (size_t)r0 * 512 + (k0) + c0);     \
        cp16(AHo[buf] + r1 * 80 + c1 * 2, Ahb + (size_t)r1 * 512 + (k0) + c1);     \
        cp16(ALo[buf] + r0 * 80 + c0 * 2, Alb + (size_t)r0 * 512 + (k0) + c0);     \
        cp16(ALo[buf] + r1 * 80 + c1 * 2, Alb + (size_t)r1 * 512 + (k0) + c1);     \
        cp16(BHo[buf] + r0 * 80 + c0 * 2, Bhb + (size_t)r0 * 512 + (k0) + c0);     \
        cp16(BLo[buf] + r0 * 80 + c0 * 2, Blb + (size_t)r0 * 512 + (k0) + c0);     \
        if (NTILE == 128) {                                                        \
            cp16(BHo[buf] + r1 * 80 + c1 * 2, Bhb + (size_t)r1 * 512 + (k0) + c1); \
            cp16(BLo[buf] + r1 * 80 + c1 * 2, Blb + (size_t)r1 * 512 + (k0) + c1); \
        }                                                                          \
        cp_commit();                                                               \
    } while (0)

    LOAD_CHUNK(0, 0);

    for (int k = 0; k < 16; k++) {
        int buf = k & 1;
        cp_wait<0>();
        __syncthreads();
        if (k < 15) LOAD_CHUNK(buf ^ 1, (k + 1) * 32);

#pragma unroll
        for (int ks2 = 0; ks2 < 2; ks2++) {
            uint32_t ksb = ks2 * 32;
            uint32_t bhf[2 * NT], blf[2 * NT];
#pragma unroll
            for (int p = 0; p < NT / 2; p++) {
                ldsm4(bhf[4 * p], bhf[4 * p + 1], bhf[4 * p + 2], bhf[4 * p + 3],
                      BHo[buf] + b_base + p * 1280 + ksb);
                ldsm4(blf[4 * p], blf[4 * p + 1], blf[4 * p + 2], blf[4 * p + 3],
                      BLo[buf] + b_base + p * 1280 + ksb);
            }
#pragma unroll
            for (int mt = 0; mt < 2; mt++) {
                uint32_t ah0, ah1, ah2, ah3, al0, al1, al2, al3;
                ldsm4(ah0, ah1, ah2, ah3, AHo[buf] + a_base + mt * 1280 + ksb);
                ldsm4(al0, al1, al2, al3, ALo[buf] + a_base + mt * 1280 + ksb);
#pragma unroll
                for (int nt = 0; nt < NT; nt++) {
                    mma16816(acc[mt][nt], ah0, ah1, ah2, ah3, bhf[2 * nt], bhf[2 * nt + 1]);
                    mma16816(acc[mt][nt], ah0, ah1, ah2, ah3, blf[2 * nt], blf[2 * nt + 1]);
                    mma16816(acc[mt][nt], al0, al1, al2, al3, bhf[2 * nt], bhf[2 * nt + 1]);
                }
            }
        }
        __syncthreads();
    }

    // ---- epilogue: per-(row, CTA-col-block) scale -> int16 ----
    float* s_rm = (float*)sm;

    float rmax[2][2];
#pragma unroll
    for (int mt = 0; mt < 2; mt++)
#pragma unroll
        for (int h = 0; h < 2; h++) {
            float m = 0.0f;
#pragma unroll
            for (int nt = 0; nt < NT; nt++)
                m = fmaxf(m, fmaxf(fabsf(acc[mt][nt][2 * h]), fabsf(acc[mt][nt][2 * h + 1])));
            m = fmaxf(m, __shfl_xor_sync(0xFFFFFFFFu, m, 1));
            m = fmaxf(m, __shfl_xor_sync(0xFFFFFFFFu, m, 2));
            rmax[mt][h] = m;
        }
    if (tig == 0) {
#pragma unroll
        for (int mt = 0; mt < 2; mt++)
#pragma unroll
            for (int h = 0; h < 2; h++)
                s_rm[(wm + mt * 16 + g + 8 * h) * 2 + (wid & 1)] = rmax[mt][h];
    }
    __syncthreads();

#pragma unroll
    for (int mt = 0; mt < 2; mt++)
#pragma unroll
        for (int h = 0; h < 2; h++) {
            int rl = wm + mt * 16 + g + 8 * h;
            float mx = fmaxf(s_rm[rl * 2 + 0], s_rm[rl * 2 + 1]);
            float inv = (mx > 0.0f) ? (32766.0f / mx) : 0.0f;
            if ((wid & 1) == 0 && tig == 0)
                QS[(size_t)(m0 + rl) * 4 + blockIdx.x] = mx * (1.0f / 32766.0f);
            size_t rowoff = (size_t)(m0 + rl) * Ncol + n0 + wn;
#pragma unroll
            for (int nt = 0; nt < NT; nt++) {
                uint32_t u0 = __float_as_uint(fmaf(acc[mt][nt][2 * h], inv, QMAGICF));
                uint32_t u1 = __float_as_uint(fmaf(acc[mt][nt][2 * h + 1], inv, QMAGICF));
                *(uint32_t*)&Q[rowoff + nt * 8 + tig * 2] = __byte_perm(u0, u1, 0x5410);
            }
        }
}

// ===========================================================================
// SpMM: int16 gather + exact per-element dequant.
// ===========================================================================
__device__ __forceinline__ void deq_fma(float4& a, float w, uint2 u) {
    uint32_t p0 = __byte_perm(u.x, 0x4B000000u, 0x7410);
    uint32_t p1 = __byte_perm(u.x, 0x4B000000u, 0x7432);
    uint32_t p2 = __byte_perm(u.y, 0x4B000000u, 0x7410);
    uint32_t p3 = __byte_perm(u.y, 0x4B000000u, 0x7432);
    a.x += w * (__uint_as_float(p0) - QMAGICF);
    a.y += w * (__uint_as_float(p1) - QMAGICF);
    a.z += w * (__uint_as_float(p2) - QMAGICF);
    a.w += w * (__uint_as_float(p3) - QMAGICF);
}

template <int NCOL, int NB, int MODE, int SHIFT>
__global__ __launch_bounds__(NCOL / 4) void k_spmm(const unsigned short* __restrict__ q,
                                                   const float* __restrict__ qs,
                                                   const float* __restrict__ bias,
                                                   float* __restrict__ outf,
                                                   __nv_bfloat16* __restrict__ oah,
                                                   __nv_bfloat16* __restrict__ oal) {
    constexpr int T = NCOL / 4;
    int row = blockIdx.x;
    int tid = threadIdx.x;

    __shared__ int   s_cols[MAXDEG];
    __shared__ float s_w[MAXDEG * NB];

    int n = g_cnt[row];
    for (int t = tid; t < n; t += T) {
        int j = g_cols[(size_t)row * MAXDEG + t];
        s_cols[t] = j;
        float dj = g_dinv[j];
#pragma unroll
        for (int b = 0; b < NB; b++) s_w[t * NB + b] = dj * qs[(size_t)j * 4 + b];
    }
    __syncthreads();

    int nb = tid >> SHIFT;
    const uint2* qp = (const uint2*)q;

    float4 acc = make_float4(0.0f, 0.0f, 0.0f, 0.0f);
    {
        float ws = g_selfcoef[row] * qs[(size_t)row * 4 + nb];
        deq_fma(acc, ws, qp[(size_t)row * T + tid]);
    }

    int t = 0;
    for (; t + 8 <= n; t += 8) {
        uint2 u[8];
        float w[8];
#pragma unroll
        for (int i = 0; i < 8; i++) {
            int j = s_cols[t + i];
            w[i] = s_w[(t + i) * NB + nb];
            u[i] = qp[(size_t)j * T + tid];
        }
#pragma unroll
        for (int i = 0; i < 8; i++) deq_fma(acc, w[i], u[i]);
    }
    for (; t < n; t++) {
        uint2 u = qp[(size_t)s_cols[t] * T + tid];
        deq_fma(acc, s_w[t * NB + nb], u);
    }

    float di = g_dinv[row];
    float4 bv = ((const float4*)bias)[tid];
    float4 r;
    r.x = di * acc.x + bv.x;
    r.y = di * acc.y + bv.y;
    r.z = di * acc.z + bv.z;
    r.w = di * acc.w + bv.w;

    if (MODE == 0) {
        ((float4*)outf)[(size_t)row * T + tid] = r;
    } else {
        r.x = fmaxf(r.x, 0.0f); r.y = fmaxf(r.y, 0.0f);
        r.z = fmaxf(r.z, 0.0f); r.w = fmaxf(r.w, 0.0f);
        float hx = __bfloat162float(__float2bfloat16_rn(r.x));
        float hy = __bfloat162float(__float2bfloat16_rn(r.y));
        float hz = __bfloat162float(__float2bfloat16_rn(r.z));
        float hw = __bfloat162float(__float2bfloat16_rn(r.w));
        ((uint2*)oah)[(size_t)row * T + tid] =
            make_uint2(packbf2(r.x, r.y), packbf2(r.z, r.w));
        ((uint2*)oal)[(size_t)row * T + tid] =
            make_uint2(packbf2(r.x - hx, r.y - hy), packbf2(r.z - hz, r.w - hw));
    }
}

// ===========================================================================
extern "C" void kernel_launch(void* const* d_in, const int* in_sizes, int n_in,
                              void* d_out, int out_size) {
    const float* x  = (const float*)d_in[0];
    const int*   ei = (const int*)d_in[1];
    const float* W1 = (const float*)d_in[2];
    const float* b1 = (const float*)d_in[3];
    const float* W2 = (const float*)d_in[4];
    const float* b2 = (const float*)d_in[5];
    const float* W3 = (const float*)d_in[6];
    const float* b3 = (const float*)d_in[7];
    float* out = (float*)d_out;

    int E = in_sizes[1] / 2;

    void *pah, *pal, *pbh, *pbl, *pq, *pqs;
    cudaGetSymbolAddress(&pah, g_ah);
    cudaGetSymbolAddress(&pal, g_al);
    cudaGetSymbolAddress(&pbh, g_bh);
    cudaGetSymbolAddress(&pbl, g_bl);
    cudaGetSymbolAddress(&pq, g_q);
    cudaGetSymbolAddress(&pqs, g_qs);
    __nv_bfloat16* ah = (__nv_bfloat16*)pah;
    __nv_bfloat16* al = (__nv_bfloat16*)pal;
    __nv_bfloat16* bh = (__nv_bfloat16*)pbh;
    __nv_bfloat16* bl = (__nv_bfloat16*)pbl;
    unsigned short* qb = (unsigned short*)pq;
    float* qsb = (float*)pqs;

    cudaFuncSetAttribute(k_gemm<128>, cudaFuncAttributeMaxDynamicSharedMemorySize, 81920);
    cudaFuncSetAttribute(k_gemm<64>,  cudaFuncAttributeMaxDynamicSharedMemorySize, 61440);

    // --- fork: graph build + W2/W3 expansion run concurrently with
    //     X/W1 expansion + GEMM1 on the main stream ---
    cudaStream_t s1;
    cudaEvent_t evFork, evJoin;
    cudaStreamCreateWithFlags(&s1, cudaStreamNonBlocking);
    cudaEventCreateWithFlags(&evFork, cudaEventDisableTiming);
    cudaEventCreateWithFlags(&evJoin, cudaEventDisableTiming);

    cudaEventRecord(evFork, 0);
    cudaStreamWaitEvent(s1, evFork, 0);
    k_clear_detect<<<2048, 256, 0, s1>>>(ei, E);
    k_scatter<<<(E + 255) / 256, 256, 0, s1>>>(ei, E);
    k_build_rows<<<NNODES / 8, 256, 0, s1>>>();
    k_expand23<<<1536, 256, 0, s1>>>(W2, W3);
    cudaEventRecord(evJoin, s1);

    // main stream: X/W1 expansion + GEMM1 (independent of side chain)
    k_expand1<<<4096 + 1024, 256>>>(x, W1);

    dim3 g512(4, 64);
    dim3 g256(4, 64);

    k_gemm<128><<<g512, 256, 81920>>>(ah, al, bh, bl, qb, qsb, 512);

    // join: SpMM1 needs the graph; GEMM2 (later) needs W2 splits
    cudaStreamWaitEvent(0, evJoin, 0);
    k_spmm<512, 4, 1, 5><<<NNODES, 128>>>(qb, qsb, b1, nullptr, ah, al);

    // layer 2
    k_gemm<128><<<g512, 256, 81920>>>(ah, al, bh + 262144, bl + 262144, qb, qsb, 512);
    k_spmm<512, 4, 1, 5><<<NNODES, 128>>>(qb, qsb, b2, nullptr, ah, al);

    // layer 3 (128x64 tiles -> 256 CTAs, 2/SM)
    k_gemm<64><<<g256, 256, 61440>>>(ah, al, bh + 524288, bl + 524288, qb, qsb, 256);
    k_spmm<256, 4, 0, 4><<<NNODES, 64>>>(qb, qsb, b3, out, nullptr, nullptr);
}